// round 3
// baseline (speedup 1.0000x reference)
#include <cuda_runtime.h>
#include <cuda_fp16.h>
#include <math.h>

#define EMB   1024
#define HID   2048
#define VOCAB 50257
#define T_STEPS 256
#define LOGIT_BLOCKS ((VOCAB + 31) / 32)   // 4 rows/warp * 8 warps = 32 rows/block

// Persistent state. h double-buffered; c in-place; g_key = packed argmax
// (orderable float bits << 32 | (0xFFFFFFFF - index)), double-buffered.
__device__ __align__(16) float g_h[2][HID];
__device__ __align__(16) float g_c[HID];
__device__ unsigned long long g_key[2];
__device__ unsigned int g_done;            // last-block-done counter (self-resetting)

// fp16 copy of W_out (206 MB scratch as __device__ global, per harness rules).
__device__ __align__(16) __half g_wout_h[(size_t)VOCAB * HID];

__device__ __forceinline__ float sigmoidf_(float x) {
    return 1.0f / (1.0f + expf(-x));
}

__device__ __forceinline__ unsigned long long pack_key(float v, int idx) {
    unsigned ub = __float_as_uint(v);
    unsigned mk = (ub & 0x80000000u) ? ~ub : (ub | 0x80000000u);  // orderable float
    return ((unsigned long long)mk << 32) | (unsigned long long)(0xFFFFFFFFu - (unsigned)idx);
}

__global__ void init_kernel() {
    int tid = blockIdx.x * blockDim.x + threadIdx.x;
    for (int i = tid; i < HID; i += 2048) {
        g_h[0][i] = 0.0f;
        g_h[1][i] = 0.0f;
        g_c[i]    = 0.0f;
    }
    if (tid == 0) {
        g_key[0] = 0ull;
        g_key[1] = 0xFFFFFFFFull;  // decodes to token 0 for step 0
        g_done   = 0u;
    }
}

// Convert W_out fp32 -> fp16. Grid exactly covers VOCAB*HID/8 threads.
__global__ void __launch_bounds__(256) wout_convert_kernel(const float* __restrict__ W_out) {
    size_t i = (size_t)blockIdx.x * 256 + threadIdx.x;   // one uint4 (8 halves) per thread
    const float4* p = (const float4*)W_out + 2 * i;
    float4 a = __ldcs(p);
    float4 b = __ldcs(p + 1);
    __half2 h0 = __floats2half2_rn(a.x, a.y);
    __half2 h1 = __floats2half2_rn(a.z, a.w);
    __half2 h2 = __floats2half2_rn(b.x, b.y);
    __half2 h3 = __floats2half2_rn(b.z, b.w);
    uint4 o;
    o.x = *(unsigned*)&h0; o.y = *(unsigned*)&h1;
    o.z = *(unsigned*)&h2; o.w = *(unsigned*)&h3;
    ((uint4*)g_wout_h)[i] = o;
}

// Gates + cell update, split-K x4: four warps per hidden index j, each covering a
// quarter of the x-dot and h-dot. Grid: 1024 blocks x 256 threads (2 j per block).
__global__ void __launch_bounds__(256) gates_cell_kernel(
    const float* __restrict__ emb,
    const float* __restrict__ W_ih,
    const float* __restrict__ W_hh,
    const float* __restrict__ b_ih,
    const float* __restrict__ b_hh,
    int t)
{
    __shared__ __align__(16) float sx[EMB];
    __shared__ __align__(16) float sh[HID];
    __shared__ float spart[8][4];

    const int tid  = threadIdx.x;
    const int lane = tid & 31;
    const int warp = tid >> 5;
    const int jl   = warp >> 2;      // 0..1: hidden index within block
    const int q    = warp & 3;       // K-quarter

    // Token from previous step's fused refine.
    unsigned long long key = g_key[(t + 1) & 1];
    int tok = (int)(0xFFFFFFFFu - (unsigned)(key & 0xFFFFFFFFull));

    // Stage x = emb[tok] and h.
    const float4* xe = (const float4*)(emb + (size_t)tok * EMB);
    ((float4*)sx)[tid] = xe[tid];                       // 256 float4 = 1024 floats
    const float4* h4 = (const float4*)(g_h[t & 1]);
    ((float4*)sh)[tid]       = h4[tid];
    ((float4*)sh)[tid + 256] = h4[tid + 256];
    __syncthreads();

    const int j = blockIdx.x * 2 + jl;                  // 0..2047

    float a0 = 0.f, a1 = 0.f, a2 = 0.f, a3 = 0.f;

    // x-dot quarter: EMB/4 = 256 floats -> 2 iters of float4 per lane.
    {
        const int base = q * (EMB / 4 / 4);             // float4 offset
        const float4* wi0 = (const float4*)(W_ih + (size_t)(j          ) * EMB) + base;
        const float4* wi1 = (const float4*)(W_ih + (size_t)(j +     HID) * EMB) + base;
        const float4* wi2 = (const float4*)(W_ih + (size_t)(j + 2 * HID) * EMB) + base;
        const float4* wi3 = (const float4*)(W_ih + (size_t)(j + 3 * HID) * EMB) + base;
        const float4* sx4 = (const float4*)sx + base;
        #pragma unroll
        for (int it = 0; it < 2; it++) {
            int idx = it * 32 + lane;
            float4 xv = sx4[idx];
            float4 v0 = __ldg(&wi0[idx]);
            float4 v1 = __ldg(&wi1[idx]);
            float4 v2 = __ldg(&wi2[idx]);
            float4 v3 = __ldg(&wi3[idx]);
            a0 += v0.x * xv.x + v0.y * xv.y + v0.z * xv.z + v0.w * xv.w;
            a1 += v1.x * xv.x + v1.y * xv.y + v1.z * xv.z + v1.w * xv.w;
            a2 += v2.x * xv.x + v2.y * xv.y + v2.z * xv.z + v2.w * xv.w;
            a3 += v3.x * xv.x + v3.y * xv.y + v3.z * xv.z + v3.w * xv.w;
        }
    }

    // h-dot quarter: HID/4 = 512 floats -> 4 iters of float4 per lane.
    {
        const int base = q * (HID / 4 / 4);
        const float4* wh0 = (const float4*)(W_hh + (size_t)(j          ) * HID) + base;
        const float4* wh1 = (const float4*)(W_hh + (size_t)(j +     HID) * HID) + base;
        const float4* wh2 = (const float4*)(W_hh + (size_t)(j + 2 * HID) * HID) + base;
        const float4* wh3 = (const float4*)(W_hh + (size_t)(j + 3 * HID) * HID) + base;
        const float4* sh4 = (const float4*)sh + base;
        #pragma unroll
        for (int it = 0; it < 4; it++) {
            int idx = it * 32 + lane;
            float4 hv = sh4[idx];
            float4 v0 = __ldg(&wh0[idx]);
            float4 v1 = __ldg(&wh1[idx]);
            float4 v2 = __ldg(&wh2[idx]);
            float4 v3 = __ldg(&wh3[idx]);
            a0 += v0.x * hv.x + v0.y * hv.y + v0.z * hv.z + v0.w * hv.w;
            a1 += v1.x * hv.x + v1.y * hv.y + v1.z * hv.z + v1.w * hv.w;
            a2 += v2.x * hv.x + v2.y * hv.y + v2.z * hv.z + v2.w * hv.w;
            a3 += v3.x * hv.x + v3.y * hv.y + v3.z * hv.z + v3.w * hv.w;
        }
    }

    #pragma unroll
    for (int off = 16; off > 0; off >>= 1) {
        a0 += __shfl_xor_sync(0xFFFFFFFFu, a0, off);
        a1 += __shfl_xor_sync(0xFFFFFFFFu, a1, off);
        a2 += __shfl_xor_sync(0xFFFFFFFFu, a2, off);
        a3 += __shfl_xor_sync(0xFFFFFFFFu, a3, off);
    }
    if (lane == 0) {
        spart[warp][0] = a0; spart[warp][1] = a1;
        spart[warp][2] = a2; spart[warp][3] = a3;
    }
    __syncthreads();

    if (tid < 2) {                                      // combine 4 quarters per j
        const int jj = blockIdx.x * 2 + tid;
        const int w0 = 4 * tid;
        float s0 = spart[w0][0] + spart[w0 + 1][0] + spart[w0 + 2][0] + spart[w0 + 3][0]
                 + b_ih[jj          ] + b_hh[jj          ];
        float s1 = spart[w0][1] + spart[w0 + 1][1] + spart[w0 + 2][1] + spart[w0 + 3][1]
                 + b_ih[jj +     HID] + b_hh[jj +     HID];
        float s2 = spart[w0][2] + spart[w0 + 1][2] + spart[w0 + 2][2] + spart[w0 + 3][2]
                 + b_ih[jj + 2 * HID] + b_hh[jj + 2 * HID];
        float s3 = spart[w0][3] + spart[w0 + 1][3] + spart[w0 + 2][3] + spart[w0 + 3][3]
                 + b_ih[jj + 3 * HID] + b_hh[jj + 3 * HID];
        float ig = sigmoidf_(s0);
        float fg = sigmoidf_(s1);
        float gg = tanhf(s2);
        float og = sigmoidf_(s3);
        float c  = fg * g_c[jj] + ig * gg;
        g_c[jj] = c;
        g_h[(t + 1) & 1][jj] = og * tanhf(c);
    }
}

// fp16 logits matvec (4 rows/warp, streaming loads) with fused last-block refine:
// the final block scans all logits for the global top-3, recomputes those exactly
// in fp32, and writes the argmax token key. Grid: LOGIT_BLOCKS x 256.
__global__ void __launch_bounds__(256) logits_fp16_kernel(
    const float* __restrict__ W_out,
    const float* __restrict__ b_out,
    float* __restrict__ out,
    int t)
{
    __shared__ __align__(16) float sh[HID];
    __shared__ unsigned long long stop[8][3];
    __shared__ unsigned long long gtop[3];
    __shared__ unsigned long long res[3];
    __shared__ int amLast;

    const int tid  = threadIdx.x;
    const int lane = tid & 31;
    const int warp = tid >> 5;

    const float4* h4 = (const float4*)(g_h[(t + 1) & 1]);
    ((float4*)sh)[tid]       = h4[tid];
    ((float4*)sh)[tid + 256] = h4[tid + 256];
    __syncthreads();

    const int vbase = blockIdx.x * 32 + warp * 4;
    // Clamp row indices for loads (uniform, branch-free); guard only the stores.
    const int r0 = min(vbase    , VOCAB - 1);
    const int r1 = min(vbase + 1, VOCAB - 1);
    const int r2 = min(vbase + 2, VOCAB - 1);
    const int r3 = min(vbase + 3, VOCAB - 1);

    const uint4* w0 = (const uint4*)(g_wout_h + (size_t)r0 * HID);
    const uint4* w1 = (const uint4*)(g_wout_h + (size_t)r1 * HID);
    const uint4* w2 = (const uint4*)(g_wout_h + (size_t)r2 * HID);
    const uint4* w3 = (const uint4*)(g_wout_h + (size_t)r3 * HID);
    const float4* sh4 = (const float4*)sh;

    float acc0 = 0.f, acc1 = 0.f, acc2 = 0.f, acc3 = 0.f;
    #pragma unroll
    for (int it = 0; it < 8; it++) {                    // 2048 halves / (32 * 8) = 8
        int idx = it * 32 + lane;
        float4 ha = sh4[2 * idx];
        float4 hb = sh4[2 * idx + 1];
        uint4 wa = __ldcs(&w0[idx]);
        uint4 wb = __ldcs(&w1[idx]);
        uint4 wc = __ldcs(&w2[idx]);
        uint4 wd = __ldcs(&w3[idx]);
        {
            float2 f0 = __half22float2(*(__half2*)&wa.x);
            float2 f1 = __half22float2(*(__half2*)&wa.y);
            float2 f2 = __half22float2(*(__half2*)&wa.z);
            float2 f3 = __half22float2(*(__half2*)&wa.w);
            acc0 += f0.x * ha.x + f0.y * ha.y + f1.x * ha.z + f1.y * ha.w
                  + f2.x * hb.x + f2.y * hb.y + f3.x * hb.z + f3.y * hb.w;
        }
        {
            float2 f0 = __half22float2(*(__half2*)&wb.x);
            float2 f1 = __half22float2(*(__half2*)&wb.y);
            float2 f2 = __half22float2(*(__half2*)&wb.z);
            float2 f3 = __half22float2(*(__half2*)&wb.w);
            acc1 += f0.x * ha.x + f0.y * ha.y + f1.x * ha.z + f1.y * ha.w
                  + f2.x * hb.x + f2.y * hb.y + f3.x * hb.z + f3.y * hb.w;
        }
        {
            float2 f0 = __half22float2(*(__half2*)&wc.x);
            float2 f1 = __half22float2(*(__half2*)&wc.y);
            float2 f2 = __half22float2(*(__half2*)&wc.z);
            float2 f3 = __half22float2(*(__half2*)&wc.w);
            acc2 += f0.x * ha.x + f0.y * ha.y + f1.x * ha.z + f1.y * ha.w
                  + f2.x * hb.x + f2.y * hb.y + f3.x * hb.z + f3.y * hb.w;
        }
        {
            float2 f0 = __half22float2(*(__half2*)&wd.x);
            float2 f1 = __half22float2(*(__half2*)&wd.y);
            float2 f2 = __half22float2(*(__half2*)&wd.z);
            float2 f3 = __half22float2(*(__half2*)&wd.w);
            acc3 += f0.x * ha.x + f0.y * ha.y + f1.x * ha.z + f1.y * ha.w
                  + f2.x * hb.x + f2.y * hb.y + f3.x * hb.z + f3.y * hb.w;
        }
    }
    #pragma unroll
    for (int off = 16; off > 0; off >>= 1) {
        acc0 += __shfl_xor_sync(0xFFFFFFFFu, acc0, off);
        acc1 += __shfl_xor_sync(0xFFFFFFFFu, acc1, off);
        acc2 += __shfl_xor_sync(0xFFFFFFFFu, acc2, off);
        acc3 += __shfl_xor_sync(0xFFFFFFFFu, acc3, off);
    }
    float* lg = out + (size_t)t * VOCAB;
    if (lane == 0) {
        if (vbase     < VOCAB) __stcs(&lg[vbase    ], acc0 + __ldg(&b_out[r0]));
        if (vbase + 1 < VOCAB) __stcs(&lg[vbase + 1], acc1 + __ldg(&b_out[r1]));
        if (vbase + 2 < VOCAB) __stcs(&lg[vbase + 2], acc2 + __ldg(&b_out[r2]));
        if (vbase + 3 < VOCAB) __stcs(&lg[vbase + 3], acc3 + __ldg(&b_out[r3]));
    }

    // ---- last-block-done: fused refine ----
    __threadfence();
    if (tid == 0) {
        unsigned v = atomicAdd(&g_done, 1u);
        amLast = (v == (unsigned)(gridDim.x - 1));
    }
    __syncthreads();
    if (!amLast) return;
    if (tid == 0) g_done = 0u;                          // reset for next step

    // Thread-local top-3 over the full logits row (keys unique per index).
    unsigned long long k0 = 0, k1 = 0, k2 = 0;
    for (int v = tid; v < VOCAB; v += 256) {
        unsigned long long key = pack_key(__ldcg(&lg[v]), v);
        if (key > k0)      { k2 = k1; k1 = k0; k0 = key; }
        else if (key > k1) { k2 = k1; k1 = key; }
        else if (key > k2) { k2 = key; }
    }
    #pragma unroll
    for (int r = 0; r < 3; r++) {
        unsigned long long m = k0;
        #pragma unroll
        for (int off = 16; off > 0; off >>= 1) {
            unsigned long long o = __shfl_xor_sync(0xFFFFFFFFu, m, off);
            if (o > m) m = o;
        }
        if (k0 == m) { k0 = k1; k1 = k2; k2 = 0; }
        if (lane == 0) stop[warp][r] = m;
    }
    __syncthreads();
    if (warp == 0) {
        k0 = (lane < 8) ? stop[lane][0] : 0;
        k1 = (lane < 8) ? stop[lane][1] : 0;
        k2 = (lane < 8) ? stop[lane][2] : 0;
        #pragma unroll
        for (int r = 0; r < 3; r++) {
            unsigned long long m = k0;
            #pragma unroll
            for (int off = 16; off > 0; off >>= 1) {
                unsigned long long o = __shfl_xor_sync(0xFFFFFFFFu, m, off);
                if (o > m) m = o;
            }
            if (k0 == m) { k0 = k1; k1 = k2; k2 = 0; }
            if (lane == 0) gtop[r] = m;
        }
    }
    __syncthreads();

    // Exact fp32 recompute for the 3 candidates (one warp each); h is in shared.
    if (warp < 3) {
        unsigned long long key = gtop[warp];
        int v = (int)(0xFFFFFFFFu - (unsigned)(key & 0xFFFFFFFFull));
        const float4* w = (const float4*)(W_out + (size_t)v * HID);
        float acc = 0.f;
        #pragma unroll
        for (int it = 0; it < 16; it++) {
            int idx = it * 32 + lane;
            float4 wv = __ldg(&w[idx]);
            float4 hv = sh4[idx];
            acc += wv.x * hv.x + wv.y * hv.y + wv.z * hv.z + wv.w * hv.w;
        }
        #pragma unroll
        for (int off = 16; off > 0; off >>= 1)
            acc += __shfl_xor_sync(0xFFFFFFFFu, acc, off);
        if (lane == 0) res[warp] = pack_key(acc + __ldg(&b_out[v]), v);
    }
    __syncthreads();
    if (tid == 0) {
        unsigned long long best = res[0];
        if (res[1] > best) best = res[1];
        if (res[2] > best) best = res[2];
        g_key[t & 1] = best;
    }
}

extern "C" void kernel_launch(void* const* d_in, const int* in_sizes, int n_in,
                              void* d_out, int out_size)
{
    const float* emb   = (const float*)d_in[0];
    const float* W_ih  = (const float*)d_in[1];
    const float* W_hh  = (const float*)d_in[2];
    const float* b_ih  = (const float*)d_in[3];
    const float* b_hh  = (const float*)d_in[4];
    const float* W_out = (const float*)d_in[5];
    const float* b_out = (const float*)d_in[6];
    float* out = (float*)d_out;

    init_kernel<<<2, 1024>>>();
    wout_convert_kernel<<<VOCAB, 256>>>(W_out);          // VOCAB*HID/8 threads exactly

    for (int t = 0; t < T_STEPS; t++) {
        gates_cell_kernel<<<1024, 256>>>(emb, W_ih, W_hh, b_ih, b_hh, t);
        logits_fp16_kernel<<<LOGIT_BLOCKS, 256>>>(W_out, b_out, out, t);
    }
}

// round 5
// speedup vs baseline: 1.1269x; 1.1269x over previous
#include <cuda_runtime.h>
#include <cuda_fp16.h>
#include <math.h>

#define EMB   1024
#define HID   2048
#define VOCAB 50257
#define T_STEPS 256

// Persistent state. h double-buffered; c in-place; g_key = packed argmax
// (orderable float bits << 32 | (0xFFFFFFFF - index)), double-buffered.
__device__ __align__(16) float g_h[2][HID];
__device__ __align__(16) float g_c[HID];
__device__ unsigned long long g_key[2];

// fp16 copy of W_out (206 MB scratch as __device__ global, per harness rules).
__device__ __align__(16) __half g_wout_h[(size_t)VOCAB * HID];

__device__ __forceinline__ float sigmoidf_(float x) {
    return 1.0f / (1.0f + expf(-x));
}

// 256-bit L2 evict-last load (ptxas on sm_103 requires v8.b32 for evict_last).
// Keeps the 96 MB of gate weights L2-resident against the evict-first W_out stream.
__device__ __forceinline__ void ldg_el8(const float* p, float4& a, float4& b) {
    unsigned x0, x1, x2, x3, x4, x5, x6, x7;
    asm volatile("ld.global.nc.L2::evict_last.v8.b32 {%0,%1,%2,%3,%4,%5,%6,%7}, [%8];"
                 : "=r"(x0), "=r"(x1), "=r"(x2), "=r"(x3),
                   "=r"(x4), "=r"(x5), "=r"(x6), "=r"(x7)
                 : "l"(p));
    a.x = __uint_as_float(x0); a.y = __uint_as_float(x1);
    a.z = __uint_as_float(x2); a.w = __uint_as_float(x3);
    b.x = __uint_as_float(x4); b.y = __uint_as_float(x5);
    b.z = __uint_as_float(x6); b.w = __uint_as_float(x7);
}

__device__ __forceinline__ unsigned long long pack_key(float v, int idx) {
    unsigned ub = __float_as_uint(v);
    unsigned mk = (ub & 0x80000000u) ? ~ub : (ub | 0x80000000u);  // orderable float
    return ((unsigned long long)mk << 32) | (unsigned long long)(0xFFFFFFFFu - (unsigned)idx);
}

__global__ void init_kernel() {
    int tid = blockIdx.x * blockDim.x + threadIdx.x;
    for (int i = tid; i < HID; i += 2048) {
        g_h[0][i] = 0.0f;
        g_h[1][i] = 0.0f;
        g_c[i]    = 0.0f;
    }
    if (tid == 0) {
        g_key[0] = 0ull;
        g_key[1] = 0xFFFFFFFFull;  // decodes to token 0 for step 0
    }
}

// Convert W_out fp32 -> fp16. Grid exactly covers VOCAB*HID/8 threads.
__global__ void __launch_bounds__(256) wout_convert_kernel(const float* __restrict__ W_out) {
    size_t i = (size_t)blockIdx.x * 256 + threadIdx.x;   // one uint4 (8 halves) per thread
    const float4* p = (const float4*)W_out + 2 * i;
    float4 a = __ldcs(p);
    float4 b = __ldcs(p + 1);
    __half2 h0 = __floats2half2_rn(a.x, a.y);
    __half2 h1 = __floats2half2_rn(a.z, a.w);
    __half2 h2 = __floats2half2_rn(b.x, b.y);
    __half2 h3 = __floats2half2_rn(b.z, b.w);
    uint4 o;
    o.x = *(unsigned*)&h0; o.y = *(unsigned*)&h1;
    o.z = *(unsigned*)&h2; o.w = *(unsigned*)&h3;
    ((uint4*)g_wout_h)[i] = o;
}

// Gates + cell update, split-K x4: four warps per hidden index j, each covering a
// quarter of the x-dot and h-dot via 256-bit evict-last loads.
// Grid: 1024 blocks x 256 threads (2 j per block).
__global__ void __launch_bounds__(256) gates_cell_kernel(
    const float* __restrict__ emb,
    const float* __restrict__ W_ih,
    const float* __restrict__ W_hh,
    const float* __restrict__ b_ih,
    const float* __restrict__ b_hh,
    int t)
{
    __shared__ __align__(16) float sx[EMB];
    __shared__ __align__(16) float sh[HID];
    __shared__ float spart[8][4];

    const int tid  = threadIdx.x;
    const int lane = tid & 31;
    const int warp = tid >> 5;
    const int jl   = warp >> 2;      // 0..1: hidden index within block
    const int q    = warp & 3;       // K-quarter

    unsigned long long key = g_key[(t + 1) & 1];
    int tok = (int)(0xFFFFFFFFu - (unsigned)(key & 0xFFFFFFFFull));

    const float4* xe = (const float4*)(emb + (size_t)tok * EMB);
    ((float4*)sx)[tid] = xe[tid];                       // 256 float4 = 1024 floats
    const float4* h4 = (const float4*)(g_h[t & 1]);
    ((float4*)sh)[tid]       = h4[tid];
    ((float4*)sh)[tid + 256] = h4[tid + 256];
    __syncthreads();

    const int j = blockIdx.x * 2 + jl;                  // 0..2047

    float a0 = 0.f, a1 = 0.f, a2 = 0.f, a3 = 0.f;

    // x-dot quarter: EMB/4 = 256 floats -> one 8-float (32B) load per lane.
    {
        const int base = q * (EMB / 4) + lane * 8;      // float offset
        const float* wi0 = W_ih + (size_t)(j          ) * EMB + base;
        const float* wi1 = W_ih + (size_t)(j +     HID) * EMB + base;
        const float* wi2 = W_ih + (size_t)(j + 2 * HID) * EMB + base;
        const float* wi3 = W_ih + (size_t)(j + 3 * HID) * EMB + base;
        float4 xa = ((const float4*)(sx + base))[0];
        float4 xb = ((const float4*)(sx + base))[1];
        float4 va, vb;
        ldg_el8(wi0, va, vb);
        a0 += va.x * xa.x + va.y * xa.y + va.z * xa.z + va.w * xa.w
            + vb.x * xb.x + vb.y * xb.y + vb.z * xb.z + vb.w * xb.w;
        ldg_el8(wi1, va, vb);
        a1 += va.x * xa.x + va.y * xa.y + va.z * xa.z + va.w * xa.w
            + vb.x * xb.x + vb.y * xb.y + vb.z * xb.z + vb.w * xb.w;
        ldg_el8(wi2, va, vb);
        a2 += va.x * xa.x + va.y * xa.y + va.z * xa.z + va.w * xa.w
            + vb.x * xb.x + vb.y * xb.y + vb.z * xb.z + vb.w * xb.w;
        ldg_el8(wi3, va, vb);
        a3 += va.x * xa.x + va.y * xa.y + va.z * xa.z + va.w * xa.w
            + vb.x * xb.x + vb.y * xb.y + vb.z * xb.z + vb.w * xb.w;
    }

    // h-dot quarter: HID/4 = 512 floats -> two 8-float loads per lane.
    {
        const int qbase = q * (HID / 4);
        const float* wh0 = W_hh + (size_t)(j          ) * HID + qbase;
        const float* wh1 = W_hh + (size_t)(j +     HID) * HID + qbase;
        const float* wh2 = W_hh + (size_t)(j + 2 * HID) * HID + qbase;
        const float* wh3 = W_hh + (size_t)(j + 3 * HID) * HID + qbase;
        #pragma unroll
        for (int it = 0; it < 2; it++) {
            const int off = it * 256 + lane * 8;        // float offset within quarter
            float4 ha = ((const float4*)(sh + qbase + off))[0];
            float4 hb = ((const float4*)(sh + qbase + off))[1];
            float4 va, vb;
            ldg_el8(wh0 + off, va, vb);
            a0 += va.x * ha.x + va.y * ha.y + va.z * ha.z + va.w * ha.w
                + vb.x * hb.x + vb.y * hb.y + vb.z * hb.z + vb.w * hb.w;
            ldg_el8(wh1 + off, va, vb);
            a1 += va.x * ha.x + va.y * ha.y + va.z * ha.z + va.w * ha.w
                + vb.x * hb.x + vb.y * hb.y + vb.z * hb.z + vb.w * hb.w;
            ldg_el8(wh2 + off, va, vb);
            a2 += va.x * ha.x + va.y * ha.y + va.z * ha.z + va.w * ha.w
                + vb.x * hb.x + vb.y * hb.y + vb.z * hb.z + vb.w * hb.w;
            ldg_el8(wh3 + off, va, vb);
            a3 += va.x * ha.x + va.y * ha.y + va.z * ha.z + va.w * ha.w
                + vb.x * hb.x + vb.y * hb.y + vb.z * hb.z + vb.w * hb.w;
        }
    }

    #pragma unroll
    for (int off = 16; off > 0; off >>= 1) {
        a0 += __shfl_xor_sync(0xFFFFFFFFu, a0, off);
        a1 += __shfl_xor_sync(0xFFFFFFFFu, a1, off);
        a2 += __shfl_xor_sync(0xFFFFFFFFu, a2, off);
        a3 += __shfl_xor_sync(0xFFFFFFFFu, a3, off);
    }
    if (lane == 0) {
        spart[warp][0] = a0; spart[warp][1] = a1;
        spart[warp][2] = a2; spart[warp][3] = a3;
    }
    __syncthreads();

    if (tid < 2) {                                      // combine 4 quarters per j
        const int jj = blockIdx.x * 2 + tid;
        const int w0 = 4 * tid;
        float s0 = spart[w0][0] + spart[w0 + 1][0] + spart[w0 + 2][0] + spart[w0 + 3][0]
                 + b_ih[jj          ] + b_hh[jj          ];
        float s1 = spart[w0][1] + spart[w0 + 1][1] + spart[w0 + 2][1] + spart[w0 + 3][1]
                 + b_ih[jj +     HID] + b_hh[jj +     HID];
        float s2 = spart[w0][2] + spart[w0 + 1][2] + spart[w0 + 2][2] + spart[w0 + 3][2]
                 + b_ih[jj + 2 * HID] + b_hh[jj + 2 * HID];
        float s3 = spart[w0][3] + spart[w0 + 1][3] + spart[w0 + 2][3] + spart[w0 + 3][3]
                 + b_ih[jj + 3 * HID] + b_hh[jj + 3 * HID];
        float ig = sigmoidf_(s0);
        float fg = sigmoidf_(s1);
        float gg = tanhf(s2);
        float og = sigmoidf_(s3);
        float c  = fg * g_c[jj] + ig * gg;
        g_c[jj] = c;
        g_h[(t + 1) & 1][jj] = og * tanhf(c);
    }
}

// fp16 logits matvec: warp handles 2 rows, streaming loads (exact R2 shape:
// regs ~32, occ ~86%, 35.7us measured). Grid: ceil(VOCAB/16) x 256.
__global__ void __launch_bounds__(256) logits_fp16_kernel(
    const float* __restrict__ b_out,
    float* __restrict__ out,
    int t)
{
    __shared__ __align__(16) float sh[HID];

    const int tid  = threadIdx.x;
    const int lane = tid & 31;
    const int warp = tid >> 5;

    const float4* h4 = (const float4*)(g_h[(t + 1) & 1]);
    ((float4*)sh)[tid]       = h4[tid];
    ((float4*)sh)[tid + 256] = h4[tid + 256];
    __syncthreads();

    const int v0 = blockIdx.x * 16 + warp * 2;
    const int v1 = v0 + 1;
    const bool p0 = v0 < VOCAB;
    const bool p1 = v1 < VOCAB;

    const uint4* w0 = (const uint4*)(g_wout_h + (size_t)v0 * HID);
    const uint4* w1 = (const uint4*)(g_wout_h + (size_t)v1 * HID);
    const float4* sh4 = (const float4*)sh;

    float acc0 = 0.f, acc1 = 0.f;
    #pragma unroll
    for (int it = 0; it < 8; it++) {                    // 2048 halves / (32 lanes * 8) = 8
        int idx = it * 32 + lane;
        float4 ha = sh4[2 * idx];
        float4 hb = sh4[2 * idx + 1];
        if (p0) {
            uint4 wv = __ldcs(&w0[idx]);
            float2 f0 = __half22float2(*(__half2*)&wv.x);
            float2 f1 = __half22float2(*(__half2*)&wv.y);
            float2 f2 = __half22float2(*(__half2*)&wv.z);
            float2 f3 = __half22float2(*(__half2*)&wv.w);
            acc0 += f0.x * ha.x + f0.y * ha.y + f1.x * ha.z + f1.y * ha.w
                  + f2.x * hb.x + f2.y * hb.y + f3.x * hb.z + f3.y * hb.w;
        }
        if (p1) {
            uint4 wv = __ldcs(&w1[idx]);
            float2 f0 = __half22float2(*(__half2*)&wv.x);
            float2 f1 = __half22float2(*(__half2*)&wv.y);
            float2 f2 = __half22float2(*(__half2*)&wv.z);
            float2 f3 = __half22float2(*(__half2*)&wv.w);
            acc1 += f0.x * ha.x + f0.y * ha.y + f1.x * ha.z + f1.y * ha.w
                  + f2.x * hb.x + f2.y * hb.y + f3.x * hb.z + f3.y * hb.w;
        }
    }
    #pragma unroll
    for (int off = 16; off > 0; off >>= 1) {
        acc0 += __shfl_xor_sync(0xFFFFFFFFu, acc0, off);
        acc1 += __shfl_xor_sync(0xFFFFFFFFu, acc1, off);
    }
    if (lane == 0 && p0) __stcs(&out[(size_t)t * VOCAB + v0], acc0 + __ldg(&b_out[v0]));
    if (lane == 0 && p1) __stcs(&out[(size_t)t * VOCAB + v1], acc1 + __ldg(&b_out[v1]));
}

// Refine: scan this step's logits for the global top-3 (packed keys, first-index
// tie rule), recompute those exactly in fp32, write the argmax token key.
__global__ void __launch_bounds__(1024) refine_kernel(
    const float* __restrict__ W_out,
    const float* __restrict__ b_out,
    const float* __restrict__ out,
    int t)
{
    __shared__ unsigned long long stop[32][3];
    __shared__ unsigned long long gtop[3];
    __shared__ unsigned long long res[3];

    const int tid  = threadIdx.x;
    const int lane = tid & 31;
    const int warp = tid >> 5;
    const float* lg = out + (size_t)t * VOCAB;

    unsigned long long k0 = 0, k1 = 0, k2 = 0;
    for (int v = tid; v < VOCAB; v += 1024) {
        unsigned long long key = pack_key(lg[v], v);
        if (key > k0)      { k2 = k1; k1 = k0; k0 = key; }
        else if (key > k1) { k2 = k1; k1 = key; }
        else if (key > k2) { k2 = key; }
    }
    #pragma unroll
    for (int r = 0; r < 3; r++) {
        unsigned long long m = k0;
        #pragma unroll
        for (int off = 16; off > 0; off >>= 1) {
            unsigned long long o = __shfl_xor_sync(0xFFFFFFFFu, m, off);
            if (o > m) m = o;
        }
        if (k0 == m) { k0 = k1; k1 = k2; k2 = 0; }
        if (lane == 0) stop[warp][r] = m;
    }
    __syncthreads();
    if (warp == 0) {
        k0 = stop[lane][0]; k1 = stop[lane][1]; k2 = stop[lane][2];
        #pragma unroll
        for (int r = 0; r < 3; r++) {
            unsigned long long m = k0;
            #pragma unroll
            for (int off = 16; off > 0; off >>= 1) {
                unsigned long long o = __shfl_xor_sync(0xFFFFFFFFu, m, off);
                if (o > m) m = o;
            }
            if (k0 == m) { k0 = k1; k1 = k2; k2 = 0; }
            if (lane == 0) gtop[r] = m;
        }
    }
    __syncthreads();

    if (warp < 3) {
        unsigned long long key = gtop[warp];
        int v = (int)(0xFFFFFFFFu - (unsigned)(key & 0xFFFFFFFFull));
        const float4* w  = (const float4*)(W_out + (size_t)v * HID);
        const float4* h4 = (const float4*)(g_h[(t + 1) & 1]);
        float acc = 0.f;
        #pragma unroll
        for (int it = 0; it < 16; it++) {
            int idx = it * 32 + lane;
            float4 wv = __ldg(&w[idx]);
            float4 hv = __ldg(&h4[idx]);
            acc += wv.x * hv.x + wv.y * hv.y + wv.z * hv.z + wv.w * hv.w;
        }
        #pragma unroll
        for (int off = 16; off > 0; off >>= 1)
            acc += __shfl_xor_sync(0xFFFFFFFFu, acc, off);
        if (lane == 0) res[warp] = pack_key(acc + __ldg(&b_out[v]), v);
    }
    __syncthreads();
    if (tid == 0) {
        unsigned long long best = res[0];
        if (res[1] > best) best = res[1];
        if (res[2] > best) best = res[2];
        g_key[t & 1] = best;
    }
}

extern "C" void kernel_launch(void* const* d_in, const int* in_sizes, int n_in,
                              void* d_out, int out_size)
{
    const float* emb   = (const float*)d_in[0];
    const float* W_ih  = (const float*)d_in[1];
    const float* W_hh  = (const float*)d_in[2];
    const float* b_ih  = (const float*)d_in[3];
    const float* b_hh  = (const float*)d_in[4];
    const float* W_out = (const float*)d_in[5];
    const float* b_out = (const float*)d_in[6];
    float* out = (float*)d_out;

    init_kernel<<<2, 1024>>>();
    wout_convert_kernel<<<VOCAB, 256>>>(W_out);          // VOCAB*HID/8 threads exactly

    const int logit_blocks = (VOCAB + 15) / 16;
    for (int t = 0; t < T_STEPS; t++) {
        gates_cell_kernel<<<1024, 256>>>(emb, W_ih, W_hh, b_ih, b_hh, t);
        logits_fp16_kernel<<<logit_blocks, 256>>>(b_out, out, t);
        refine_kernel<<<1, 1024>>>(W_out, b_out, out, t);
    }
}

// round 7
// speedup vs baseline: 1.2920x; 1.1465x over previous
#include <cuda_runtime.h>
#include <cuda_fp16.h>
#include <math.h>

#define EMB   1024
#define HID   2048
#define VOCAB 50257
#define T_STEPS 256
#define GH_BLOCKS 512
#define LOGIT_BLOCKS ((VOCAB + 15) / 16)
#define FUSED_BLOCKS (GH_BLOCKS + LOGIT_BLOCKS)
#define REFINE_BLOCKS 32
#define REFINE_CHUNK ((VOCAB + REFINE_BLOCKS - 1) / REFINE_BLOCKS)

// Persistent state. h double-buffered; c in-place; g_key = packed argmax
// (orderable float bits << 32 | (0xFFFFFFFF - index)), double-buffered.
__device__ __align__(16) float g_h[2][HID];
__device__ __align__(16) float g_c[HID];
__device__ unsigned long long g_key[2];
__device__ __align__(16) float g_gh[4 * HID];   // h . W_hh partials (row-indexed)

// fp16 copy of W_out (206 MB scratch as __device__ global, per harness rules).
__device__ __align__(16) __half g_wout_h[(size_t)VOCAB * HID];

__device__ __forceinline__ float sigmoidf_(float x) {
    return 1.0f / (1.0f + expf(-x));
}

// 256-bit loads (sm_103 requires v8.b32 with L2 eviction-policy modifiers).
__device__ __forceinline__ void ldg_el8(const float* p, float4& a, float4& b) {
    unsigned x0, x1, x2, x3, x4, x5, x6, x7;
    asm volatile("ld.global.nc.L2::evict_last.v8.b32 {%0,%1,%2,%3,%4,%5,%6,%7}, [%8];"
                 : "=r"(x0), "=r"(x1), "=r"(x2), "=r"(x3),
                   "=r"(x4), "=r"(x5), "=r"(x6), "=r"(x7)
                 : "l"(p));
    a.x = __uint_as_float(x0); a.y = __uint_as_float(x1);
    a.z = __uint_as_float(x2); a.w = __uint_as_float(x3);
    b.x = __uint_as_float(x4); b.y = __uint_as_float(x5);
    b.z = __uint_as_float(x6); b.w = __uint_as_float(x7);
}

__device__ __forceinline__ void ldg_ef8(const __half* p, unsigned* x) {
    asm volatile("ld.global.nc.L2::evict_first.v8.b32 {%0,%1,%2,%3,%4,%5,%6,%7}, [%8];"
                 : "=r"(x[0]), "=r"(x[1]), "=r"(x[2]), "=r"(x[3]),
                   "=r"(x[4]), "=r"(x[5]), "=r"(x[6]), "=r"(x[7])
                 : "l"(p));
}

__device__ __forceinline__ unsigned long long pack_key(float v, int idx) {
    unsigned ub = __float_as_uint(v);
    unsigned mk = (ub & 0x80000000u) ? ~ub : (ub | 0x80000000u);  // orderable float
    return ((unsigned long long)mk << 32) | (unsigned long long)(0xFFFFFFFFu - (unsigned)idx);
}

__global__ void init_kernel() {
    int tid = blockIdx.x * blockDim.x + threadIdx.x;
    for (int i = tid; i < HID; i += 2048) {
        g_h[0][i] = 0.0f;
        g_h[1][i] = 0.0f;
        g_c[i]    = 0.0f;
    }
    for (int i = tid; i < 4 * HID; i += 2048) g_gh[i] = 0.0f;  // h0 = 0 -> gh = 0
    if (tid == 0) {
        g_key[0] = 0ull;
        g_key[1] = 0xFFFFFFFFull;  // decodes to token 0 for step 0
    }
}

// Convert W_out fp32 -> fp16. Grid exactly covers VOCAB*HID/8 threads.
__global__ void __launch_bounds__(256) wout_convert_kernel(const float* __restrict__ W_out) {
    size_t i = (size_t)blockIdx.x * 256 + threadIdx.x;   // one uint4 (8 halves) per thread
    const float4* p = (const float4*)W_out + 2 * i;
    float4 a = __ldcs(p);
    float4 b = __ldcs(p + 1);
    __half2 h0 = __floats2half2_rn(a.x, a.y);
    __half2 h1 = __floats2half2_rn(a.z, a.w);
    __half2 h2 = __floats2half2_rn(b.x, b.y);
    __half2 h3 = __floats2half2_rn(b.z, b.w);
    uint4 o;
    o.x = *(unsigned*)&h0; o.y = *(unsigned*)&h1;
    o.z = *(unsigned*)&h2; o.w = *(unsigned*)&h3;
    ((uint4*)g_wout_h)[i] = o;
}

// gates_x_cell: x . W_ih + gh + biases -> nonlinearities -> h, c.
// Also resets the argmax accumulator this step's refine will use.
// Grid: 512 blocks x 256 threads (4 j per block, split-K x2).
__global__ void __launch_bounds__(256) gates_x_cell_kernel(
    const float* __restrict__ emb,
    const float* __restrict__ W_ih,
    const float* __restrict__ b_ih,
    const float* __restrict__ b_hh,
    int t)
{
    __shared__ __align__(16) float sx[EMB];
    __shared__ float spart[8][4];

    const int tid  = threadIdx.x;
    const int lane = tid & 31;
    const int warp = tid >> 5;
    const int jl   = warp >> 1;
    const int half = warp & 1;

    unsigned long long key = g_key[(t + 1) & 1];
    int tok = (int)(0xFFFFFFFFu - (unsigned)(key & 0xFFFFFFFFull));
    if (blockIdx.x == 0 && tid == 0) g_key[t & 1] = 0ull;  // refine(t) accumulates here

    const float4* xe = (const float4*)(emb + (size_t)tok * EMB);
    ((float4*)sx)[tid] = xe[tid];
    __syncthreads();

    const int j = blockIdx.x * 4 + jl;
    const int base = half * (EMB / 2);

    float a0 = 0.f, a1 = 0.f, a2 = 0.f, a3 = 0.f;
    const float* wi0 = W_ih + (size_t)(j          ) * EMB + base;
    const float* wi1 = W_ih + (size_t)(j +     HID) * EMB + base;
    const float* wi2 = W_ih + (size_t)(j + 2 * HID) * EMB + base;
    const float* wi3 = W_ih + (size_t)(j + 3 * HID) * EMB + base;
    #pragma unroll
    for (int it = 0; it < 2; it++) {                    // 512 floats / (32*8)
        const int off = it * 256 + lane * 8;
        float4 xa = ((const float4*)(sx + base + off))[0];
        float4 xb = ((const float4*)(sx + base + off))[1];
        float4 va, vb;
        ldg_el8(wi0 + off, va, vb);
        a0 += va.x * xa.x + va.y * xa.y + va.z * xa.z + va.w * xa.w
            + vb.x * xb.x + vb.y * xb.y + vb.z * xb.z + vb.w * xb.w;
        ldg_el8(wi1 + off, va, vb);
        a1 += va.x * xa.x + va.y * xa.y + va.z * xa.z + va.w * xa.w
            + vb.x * xb.x + vb.y * xb.y + vb.z * xb.z + vb.w * xb.w;
        ldg_el8(wi2 + off, va, vb);
        a2 += va.x * xa.x + va.y * xa.y + va.z * xa.z + va.w * xa.w
            + vb.x * xb.x + vb.y * xb.y + vb.z * xb.z + vb.w * xb.w;
        ldg_el8(wi3 + off, va, vb);
        a3 += va.x * xa.x + va.y * xa.y + va.z * xa.z + va.w * xa.w
            + vb.x * xb.x + vb.y * xb.y + vb.z * xb.z + vb.w * xb.w;
    }

    #pragma unroll
    for (int off = 16; off > 0; off >>= 1) {
        a0 += __shfl_xor_sync(0xFFFFFFFFu, a0, off);
        a1 += __shfl_xor_sync(0xFFFFFFFFu, a1, off);
        a2 += __shfl_xor_sync(0xFFFFFFFFu, a2, off);
        a3 += __shfl_xor_sync(0xFFFFFFFFu, a3, off);
    }
    if (lane == 0) {
        spart[warp][0] = a0; spart[warp][1] = a1;
        spart[warp][2] = a2; spart[warp][3] = a3;
    }
    __syncthreads();

    if (tid < 4) {
        const int jj = blockIdx.x * 4 + tid;
        const int w0 = 2 * tid;
        float s0 = spart[w0][0] + spart[w0 + 1][0] + g_gh[jj          ]
                 + b_ih[jj          ] + b_hh[jj          ];
        float s1 = spart[w0][1] + spart[w0 + 1][1] + g_gh[jj +     HID]
                 + b_ih[jj +     HID] + b_hh[jj +     HID];
        float s2 = spart[w0][2] + spart[w0 + 1][2] + g_gh[jj + 2 * HID]
                 + b_ih[jj + 2 * HID] + b_hh[jj + 2 * HID];
        float s3 = spart[w0][3] + spart[w0 + 1][3] + g_gh[jj + 3 * HID]
                 + b_ih[jj + 3 * HID] + b_hh[jj + 3 * HID];
        float ig = sigmoidf_(s0);
        float fg = sigmoidf_(s1);
        float gg = tanhf(s2);
        float og = sigmoidf_(s3);
        float c  = fg * g_c[jj] + ig * gg;
        g_c[jj] = c;
        g_h[(t + 1) & 1][jj] = og * tanhf(c);
    }
}

// Fused kernel: blocks [0, GH_BLOCKS) compute gh = h(t+1) . W_hh (feeds step t+1);
// blocks [GH_BLOCKS, FUSED_BLOCKS) compute this step's fp16 logits. Both depend
// only on h(t+1); fusing them into one grid overlaps the 64 MB W_hh stream with
// the 206 MB W_out stream on a single CUDA stream (no stream objects allowed).
__global__ void __launch_bounds__(256) fused_logits_gh_kernel(
    const float* __restrict__ W_hh,
    const float* __restrict__ b_out,
    float* __restrict__ out,
    int t)
{
    __shared__ __align__(16) float sh[HID];
    __shared__ float spart[8][4];

    const int tid  = threadIdx.x;
    const int lane = tid & 31;
    const int warp = tid >> 5;

    const float4* h4 = (const float4*)(g_h[(t + 1) & 1]);
    ((float4*)sh)[tid]       = h4[tid];
    ((float4*)sh)[tid + 256] = h4[tid + 256];
    __syncthreads();

    if (blockIdx.x < GH_BLOCKS) {
        // ---- gh part: 4 j per block, split-K x2 ----
        const int jl   = warp >> 1;
        const int half = warp & 1;
        const int j    = blockIdx.x * 4 + jl;
        const int base = half * (HID / 2);

        float a0 = 0.f, a1 = 0.f, a2 = 0.f, a3 = 0.f;
        const float* wh0 = W_hh + (size_t)(j          ) * HID + base;
        const float* wh1 = W_hh + (size_t)(j +     HID) * HID + base;
        const float* wh2 = W_hh + (size_t)(j + 2 * HID) * HID + base;
        const float* wh3 = W_hh + (size_t)(j + 3 * HID) * HID + base;
        #pragma unroll
        for (int it = 0; it < 4; it++) {                // 1024 floats / (32*8)
            const int off = it * 256 + lane * 8;
            float4 ha = ((const float4*)(sh + base + off))[0];
            float4 hb = ((const float4*)(sh + base + off))[1];
            float4 va, vb;
            ldg_el8(wh0 + off, va, vb);
            a0 += va.x * ha.x + va.y * ha.y + va.z * ha.z + va.w * ha.w
                + vb.x * hb.x + vb.y * hb.y + vb.z * hb.z + vb.w * hb.w;
            ldg_el8(wh1 + off, va, vb);
            a1 += va.x * ha.x + va.y * ha.y + va.z * ha.z + va.w * ha.w
                + vb.x * hb.x + vb.y * hb.y + vb.z * hb.z + vb.w * hb.w;
            ldg_el8(wh2 + off, va, vb);
            a2 += va.x * ha.x + va.y * ha.y + va.z * ha.z + va.w * ha.w
                + vb.x * hb.x + vb.y * hb.y + vb.z * hb.z + vb.w * hb.w;
            ldg_el8(wh3 + off, va, vb);
            a3 += va.x * ha.x + va.y * ha.y + va.z * ha.z + va.w * ha.w
                + vb.x * hb.x + vb.y * hb.y + vb.z * hb.z + vb.w * hb.w;
        }

        #pragma unroll
        for (int off = 16; off > 0; off >>= 1) {
            a0 += __shfl_xor_sync(0xFFFFFFFFu, a0, off);
            a1 += __shfl_xor_sync(0xFFFFFFFFu, a1, off);
            a2 += __shfl_xor_sync(0xFFFFFFFFu, a2, off);
            a3 += __shfl_xor_sync(0xFFFFFFFFu, a3, off);
        }
        if (lane == 0) {
            spart[warp][0] = a0; spart[warp][1] = a1;
            spart[warp][2] = a2; spart[warp][3] = a3;
        }
        __syncthreads();

        if (tid < 4) {
            const int jj = blockIdx.x * 4 + tid;
            const int w0 = 2 * tid;
            g_gh[jj          ] = spart[w0][0] + spart[w0 + 1][0];
            g_gh[jj +     HID] = spart[w0][1] + spart[w0 + 1][1];
            g_gh[jj + 2 * HID] = spart[w0][2] + spart[w0 + 1][2];
            g_gh[jj + 3 * HID] = spart[w0][3] + spart[w0 + 1][3];
        }
        return;
    }

    // ---- logits part: 2 rows/warp, 256-bit evict-first loads ----
    const int lb = blockIdx.x - GH_BLOCKS;
    const int v0 = lb * 16 + warp * 2;
    const int v1 = v0 + 1;
    const bool p0 = v0 < VOCAB;
    const bool p1 = v1 < VOCAB;

    const __half* w0 = g_wout_h + (size_t)v0 * HID;
    const __half* w1 = g_wout_h + (size_t)v1 * HID;

    float acc0 = 0.f, acc1 = 0.f;
    #pragma unroll
    for (int it = 0; it < 4; it++) {                    // 2048 halves / (32 lanes * 16)
        const int hoff = it * 512 + lane * 16;
        float4 hv0 = ((const float4*)(sh + hoff))[0];
        float4 hv1 = ((const float4*)(sh + hoff))[1];
        float4 hv2 = ((const float4*)(sh + hoff))[2];
        float4 hv3 = ((const float4*)(sh + hoff))[3];
        if (p0) {
            unsigned wr[8];
            ldg_ef8(w0 + hoff, wr);
            float2 f0 = __half22float2(*(__half2*)&wr[0]);
            float2 f1 = __half22float2(*(__half2*)&wr[1]);
            float2 f2 = __half22float2(*(__half2*)&wr[2]);
            float2 f3 = __half22float2(*(__half2*)&wr[3]);
            float2 f4 = __half22float2(*(__half2*)&wr[4]);
            float2 f5 = __half22float2(*(__half2*)&wr[5]);
            float2 f6 = __half22float2(*(__half2*)&wr[6]);
            float2 f7 = __half22float2(*(__half2*)&wr[7]);
            acc0 += f0.x * hv0.x + f0.y * hv0.y + f1.x * hv0.z + f1.y * hv0.w
                  + f2.x * hv1.x + f2.y * hv1.y + f3.x * hv1.z + f3.y * hv1.w
                  + f4.x * hv2.x + f4.y * hv2.y + f5.x * hv2.z + f5.y * hv2.w
                  + f6.x * hv3.x + f6.y * hv3.y + f7.x * hv3.z + f7.y * hv3.w;
        }
        if (p1) {
            unsigned wr[8];
            ldg_ef8(w1 + hoff, wr);
            float2 f0 = __half22float2(*(__half2*)&wr[0]);
            float2 f1 = __half22float2(*(__half2*)&wr[1]);
            float2 f2 = __half22float2(*(__half2*)&wr[2]);
            float2 f3 = __half22float2(*(__half2*)&wr[3]);
            float2 f4 = __half22float2(*(__half2*)&wr[4]);
            float2 f5 = __half22float2(*(__half2*)&wr[5]);
            float2 f6 = __half22float2(*(__half2*)&wr[6]);
            float2 f7 = __half22float2(*(__half2*)&wr[7]);
            acc1 += f0.x * hv0.x + f0.y * hv0.y + f1.x * hv0.z + f1.y * hv0.w
                  + f2.x * hv1.x + f2.y * hv1.y + f3.x * hv1.z + f3.y * hv1.w
                  + f4.x * hv2.x + f4.y * hv2.y + f5.x * hv2.z + f5.y * hv2.w
                  + f6.x * hv3.x + f6.y * hv3.y + f7.x * hv3.z + f7.y * hv3.w;
        }
    }
    #pragma unroll
    for (int off = 16; off > 0; off >>= 1) {
        acc0 += __shfl_xor_sync(0xFFFFFFFFu, acc0, off);
        acc1 += __shfl_xor_sync(0xFFFFFFFFu, acc1, off);
    }
    if (lane == 0 && p0) __stcs(&out[(size_t)t * VOCAB + v0], acc0 + __ldg(&b_out[v0]));
    if (lane == 0 && p1) __stcs(&out[(size_t)t * VOCAB + v1], acc1 + __ldg(&b_out[v1]));
}

// Parallel refine: each of 32 blocks finds its slice's approx-top-3, recomputes
// those exactly in fp32, and atomicMaxes the exact packed key. Global result =
// exact argmax with first-index tie rule. Grid: REFINE_BLOCKS x 256.
__global__ void __launch_bounds__(256) refine_kernel(
    const float* __restrict__ W_out,
    const float* __restrict__ b_out,
    const float* __restrict__ out,
    int t)
{
    __shared__ unsigned long long stop[8][3];
    __shared__ unsigned long long gtop[3];
    __shared__ unsigned long long res[3];

    const int tid  = threadIdx.x;
    const int lane = tid & 31;
    const int warp = tid >> 5;
    const float* lg = out + (size_t)t * VOCAB;

    const int vbeg = blockIdx.x * REFINE_CHUNK;
    const int vend = min(vbeg + REFINE_CHUNK, VOCAB);

    unsigned long long k0 = 0, k1 = 0, k2 = 0;
    for (int v = vbeg + tid; v < vend; v += 256) {
        unsigned long long key = pack_key(__ldcg(&lg[v]), v);
        if (key > k0)      { k2 = k1; k1 = k0; k0 = key; }
        else if (key > k1) { k2 = k1; k1 = key; }
        else if (key > k2) { k2 = key; }
    }
    #pragma unroll
    for (int r = 0; r < 3; r++) {
        unsigned long long m = k0;
        #pragma unroll
        for (int off = 16; off > 0; off >>= 1) {
            unsigned long long o = __shfl_xor_sync(0xFFFFFFFFu, m, off);
            if (o > m) m = o;
        }
        if (k0 == m) { k0 = k1; k1 = k2; k2 = 0; }
        if (lane == 0) stop[warp][r] = m;
    }
    __syncthreads();
    if (warp == 0) {
        k0 = (lane < 8) ? stop[lane][0] : 0;
        k1 = (lane < 8) ? stop[lane][1] : 0;
        k2 = (lane < 8) ? stop[lane][2] : 0;
        #pragma unroll
        for (int r = 0; r < 3; r++) {
            unsigned long long m = k0;
            #pragma unroll
            for (int off = 16; off > 0; off >>= 1) {
                unsigned long long o = __shfl_xor_sync(0xFFFFFFFFu, m, off);
                if (o > m) m = o;
            }
            if (k0 == m) { k0 = k1; k1 = k2; k2 = 0; }
            if (lane == 0) gtop[r] = m;
        }
    }
    __syncthreads();

    if (warp < 3) {
        unsigned long long key = gtop[warp];
        int v = (int)(0xFFFFFFFFu - (unsigned)(key & 0xFFFFFFFFull));
        const float4* w  = (const float4*)(W_out + (size_t)v * HID);
        const float4* h4 = (const float4*)(g_h[(t + 1) & 1]);
        float acc = 0.f;
        #pragma unroll
        for (int it = 0; it < 16; it++) {
            int idx = it * 32 + lane;
            float4 wv = __ldg(&w[idx]);
            float4 hv = __ldg(&h4[idx]);
            acc += wv.x * hv.x + wv.y * hv.y + wv.z * hv.z + wv.w * hv.w;
        }
        #pragma unroll
        for (int off = 16; off > 0; off >>= 1)
            acc += __shfl_xor_sync(0xFFFFFFFFu, acc, off);
        if (lane == 0) res[warp] = pack_key(acc + __ldg(&b_out[v]), v);
    }
    __syncthreads();
    if (tid == 0) {
        unsigned long long best = res[0];
        if (res[1] > best) best = res[1];
        if (res[2] > best) best = res[2];
        atomicMax(&g_key[t & 1], best);
    }
}

extern "C" void kernel_launch(void* const* d_in, const int* in_sizes, int n_in,
                              void* d_out, int out_size)
{
    const float* emb   = (const float*)d_in[0];
    const float* W_ih  = (const float*)d_in[1];
    const float* W_hh  = (const float*)d_in[2];
    const float* b_ih  = (const float*)d_in[3];
    const float* b_hh  = (const float*)d_in[4];
    const float* W_out = (const float*)d_in[5];
    const float* b_out = (const float*)d_in[6];
    float* out = (float*)d_out;

    init_kernel<<<2, 1024>>>();
    wout_convert_kernel<<<VOCAB, 256>>>(W_out);

    for (int t = 0; t < T_STEPS; t++) {
        gates_x_cell_kernel<<<512, 256>>>(emb, W_ih, b_ih, b_hh, t);
        fused_logits_gh_kernel<<<FUSED_BLOCKS, 256>>>(W_hh, b_out, out, t);
        refine_kernel<<<REFINE_BLOCKS, 256>>>(W_out, b_out, out, t);
    }
}

// round 8
// speedup vs baseline: 1.3531x; 1.0473x over previous
#include <cuda_runtime.h>
#include <cuda_fp16.h>
#include <math.h>

#define EMB   1024
#define HID   2048
#define VOCAB 50257
#define T_STEPS 256
#define GH_BLOCKS 512
#define LOGIT_BLOCKS ((VOCAB + 15) / 16)
#define FUSED_BLOCKS (GH_BLOCKS + LOGIT_BLOCKS)
#define REFINE_BLOCKS 32
#define REFINE_CHUNK ((VOCAB + REFINE_BLOCKS - 1) / REFINE_BLOCKS)

// Persistent state. h double-buffered; c in-place; g_key = packed argmax
// (orderable float bits << 32 | (0xFFFFFFFF - index)), double-buffered.
__device__ __align__(16) float g_h[2][HID];
__device__ __align__(16) float g_c[HID];
__device__ unsigned long long g_key[2];
__device__ __align__(16) float g_gh[4 * HID];   // h . W_hh partials (row-indexed)

// fp16 copy of W_out (206 MB scratch as __device__ global, per harness rules).
__device__ __align__(16) __half g_wout_h[(size_t)VOCAB * HID];

__device__ __forceinline__ float sigmoidf_(float x) {
    return 1.0f / (1.0f + expf(-x));
}

__device__ __forceinline__ unsigned long long pack_key(float v, int idx) {
    unsigned ub = __float_as_uint(v);
    unsigned mk = (ub & 0x80000000u) ? ~ub : (ub | 0x80000000u);  // orderable float
    return ((unsigned long long)mk << 32) | (unsigned long long)(0xFFFFFFFFu - (unsigned)idx);
}

__global__ void init_kernel() {
    int tid = blockIdx.x * blockDim.x + threadIdx.x;
    for (int i = tid; i < HID; i += 2048) {
        g_h[0][i] = 0.0f;
        g_h[1][i] = 0.0f;
        g_c[i]    = 0.0f;
    }
    for (int i = tid; i < 4 * HID; i += 2048) g_gh[i] = 0.0f;  // h0 = 0 -> gh = 0
    if (tid == 0) {
        g_key[0] = 0ull;
        g_key[1] = 0xFFFFFFFFull;  // decodes to token 0 for step 0
    }
}

// Convert W_out fp32 -> fp16. Grid exactly covers VOCAB*HID/8 threads.
__global__ void __launch_bounds__(256) wout_convert_kernel(const float* __restrict__ W_out) {
    size_t i = (size_t)blockIdx.x * 256 + threadIdx.x;   // one uint4 (8 halves) per thread
    const float4* p = (const float4*)W_out + 2 * i;
    float4 a = __ldcs(p);
    float4 b = __ldcs(p + 1);
    __half2 h0 = __floats2half2_rn(a.x, a.y);
    __half2 h1 = __floats2half2_rn(a.z, a.w);
    __half2 h2 = __floats2half2_rn(b.x, b.y);
    __half2 h3 = __floats2half2_rn(b.z, b.w);
    uint4 o;
    o.x = *(unsigned*)&h0; o.y = *(unsigned*)&h1;
    o.z = *(unsigned*)&h2; o.w = *(unsigned*)&h3;
    ((uint4*)g_wout_h)[i] = o;
}

// gates_x_cell: x . W_ih + gh + biases -> nonlinearities -> h, c.
// Also resets the argmax accumulator this step's refine will use.
// Grid: 512 blocks x 256 threads (4 j per block, split-K x2).
__global__ void __launch_bounds__(256) gates_x_cell_kernel(
    const float* __restrict__ emb,
    const float* __restrict__ W_ih,
    const float* __restrict__ b_ih,
    const float* __restrict__ b_hh,
    int t)
{
    __shared__ __align__(16) float sx[EMB];
    __shared__ float spart[8][4];

    const int tid  = threadIdx.x;
    const int lane = tid & 31;
    const int warp = tid >> 5;
    const int jl   = warp >> 1;
    const int half = warp & 1;

    unsigned long long key = g_key[(t + 1) & 1];
    int tok = (int)(0xFFFFFFFFu - (unsigned)(key & 0xFFFFFFFFull));
    if (blockIdx.x == 0 && tid == 0) g_key[t & 1] = 0ull;  // refine(t) accumulates here

    const float4* xe = (const float4*)(emb + (size_t)tok * EMB);
    ((float4*)sx)[tid] = xe[tid];
    __syncthreads();

    const int j = blockIdx.x * 4 + jl;
    const int base4 = half * (EMB / 2 / 4);             // float4 offset

    float a0 = 0.f, a1 = 0.f, a2 = 0.f, a3 = 0.f;
    const float4* wi0 = (const float4*)(W_ih + (size_t)(j          ) * EMB) + base4;
    const float4* wi1 = (const float4*)(W_ih + (size_t)(j +     HID) * EMB) + base4;
    const float4* wi2 = (const float4*)(W_ih + (size_t)(j + 2 * HID) * EMB) + base4;
    const float4* wi3 = (const float4*)(W_ih + (size_t)(j + 3 * HID) * EMB) + base4;
    const float4* sx4 = (const float4*)sx + base4;
    #pragma unroll
    for (int it = 0; it < 4; it++) {                    // 512 floats / (32*4) = 4
        int idx = it * 32 + lane;
        float4 xv = sx4[idx];
        float4 v0 = __ldg(&wi0[idx]);
        float4 v1 = __ldg(&wi1[idx]);
        float4 v2 = __ldg(&wi2[idx]);
        float4 v3 = __ldg(&wi3[idx]);
        a0 += v0.x * xv.x + v0.y * xv.y + v0.z * xv.z + v0.w * xv.w;
        a1 += v1.x * xv.x + v1.y * xv.y + v1.z * xv.z + v1.w * xv.w;
        a2 += v2.x * xv.x + v2.y * xv.y + v2.z * xv.z + v2.w * xv.w;
        a3 += v3.x * xv.x + v3.y * xv.y + v3.z * xv.z + v3.w * xv.w;
    }

    #pragma unroll
    for (int off = 16; off > 0; off >>= 1) {
        a0 += __shfl_xor_sync(0xFFFFFFFFu, a0, off);
        a1 += __shfl_xor_sync(0xFFFFFFFFu, a1, off);
        a2 += __shfl_xor_sync(0xFFFFFFFFu, a2, off);
        a3 += __shfl_xor_sync(0xFFFFFFFFu, a3, off);
    }
    if (lane == 0) {
        spart[warp][0] = a0; spart[warp][1] = a1;
        spart[warp][2] = a2; spart[warp][3] = a3;
    }
    __syncthreads();

    if (tid < 4) {
        const int jj = blockIdx.x * 4 + tid;
        const int w0 = 2 * tid;
        float s0 = spart[w0][0] + spart[w0 + 1][0] + g_gh[jj          ]
                 + b_ih[jj          ] + b_hh[jj          ];
        float s1 = spart[w0][1] + spart[w0 + 1][1] + g_gh[jj +     HID]
                 + b_ih[jj +     HID] + b_hh[jj +     HID];
        float s2 = spart[w0][2] + spart[w0 + 1][2] + g_gh[jj + 2 * HID]
                 + b_ih[jj + 2 * HID] + b_hh[jj + 2 * HID];
        float s3 = spart[w0][3] + spart[w0 + 1][3] + g_gh[jj + 3 * HID]
                 + b_ih[jj + 3 * HID] + b_hh[jj + 3 * HID];
        float ig = sigmoidf_(s0);
        float fg = sigmoidf_(s1);
        float gg = tanhf(s2);
        float og = sigmoidf_(s3);
        float c  = fg * g_c[jj] + ig * gg;
        g_c[jj] = c;
        g_h[(t + 1) & 1][jj] = og * tanhf(c);
    }
}

// Fused kernel: blocks [0, GH_BLOCKS) compute gh = h(t+1) . W_hh (feeds step t+1);
// blocks [GH_BLOCKS, FUSED_BLOCKS) compute this step's fp16 logits. Both depend
// only on h(t+1). __launch_bounds__(256, 6) caps registers so the logits stream
// keeps high occupancy; any spill lands in the latency-tolerant gh branch.
__global__ void __launch_bounds__(256, 6) fused_logits_gh_kernel(
    const float* __restrict__ W_hh,
    const float* __restrict__ b_out,
    float* __restrict__ out,
    int t)
{
    __shared__ __align__(16) float sh[HID];
    __shared__ float spart[8][4];

    const int tid  = threadIdx.x;
    const int lane = tid & 31;
    const int warp = tid >> 5;

    const float4* h4 = (const float4*)(g_h[(t + 1) & 1]);
    ((float4*)sh)[tid]       = h4[tid];
    ((float4*)sh)[tid + 256] = h4[tid + 256];
    __syncthreads();

    const float4* sh4 = (const float4*)sh;

    if (blockIdx.x < GH_BLOCKS) {
        // ---- gh part: 4 j per block, split-K x2, plain float4 __ldg ----
        const int jl   = warp >> 1;
        const int half = warp & 1;
        const int j    = blockIdx.x * 4 + jl;
        const int base4 = half * (HID / 2 / 4);         // float4 offset

        float a0 = 0.f, a1 = 0.f, a2 = 0.f, a3 = 0.f;
        const float4* wh0 = (const float4*)(W_hh + (size_t)(j          ) * HID) + base4;
        const float4* wh1 = (const float4*)(W_hh + (size_t)(j +     HID) * HID) + base4;
        const float4* wh2 = (const float4*)(W_hh + (size_t)(j + 2 * HID) * HID) + base4;
        const float4* wh3 = (const float4*)(W_hh + (size_t)(j + 3 * HID) * HID) + base4;
        const float4* shq = sh4 + base4;
        #pragma unroll
        for (int it = 0; it < 8; it++) {                // 1024 floats / (32*4) = 8
            int idx = it * 32 + lane;
            float4 hv = shq[idx];
            float4 v0 = __ldg(&wh0[idx]);
            float4 v1 = __ldg(&wh1[idx]);
            float4 v2 = __ldg(&wh2[idx]);
            float4 v3 = __ldg(&wh3[idx]);
            a0 += v0.x * hv.x + v0.y * hv.y + v0.z * hv.z + v0.w * hv.w;
            a1 += v1.x * hv.x + v1.y * hv.y + v1.z * hv.z + v1.w * hv.w;
            a2 += v2.x * hv.x + v2.y * hv.y + v2.z * hv.z + v2.w * hv.w;
            a3 += v3.x * hv.x + v3.y * hv.y + v3.z * hv.z + v3.w * hv.w;
        }

        #pragma unroll
        for (int off = 16; off > 0; off >>= 1) {
            a0 += __shfl_xor_sync(0xFFFFFFFFu, a0, off);
            a1 += __shfl_xor_sync(0xFFFFFFFFu, a1, off);
            a2 += __shfl_xor_sync(0xFFFFFFFFu, a2, off);
            a3 += __shfl_xor_sync(0xFFFFFFFFu, a3, off);
        }
        if (lane == 0) {
            spart[warp][0] = a0; spart[warp][1] = a1;
            spart[warp][2] = a2; spart[warp][3] = a3;
        }
        __syncthreads();

        if (tid < 4) {
            const int jj = blockIdx.x * 4 + tid;
            const int w0 = 2 * tid;
            g_gh[jj          ] = spart[w0][0] + spart[w0 + 1][0];
            g_gh[jj +     HID] = spart[w0][1] + spart[w0 + 1][1];
            g_gh[jj + 2 * HID] = spart[w0][2] + spart[w0 + 1][2];
            g_gh[jj + 3 * HID] = spart[w0][3] + spart[w0 + 1][3];
        }
        return;
    }

    // ---- logits part: 2 rows/warp, uint4 __ldcs streaming loads (R2 shape) ----
    const int lb = blockIdx.x - GH_BLOCKS;
    const int v0 = lb * 16 + warp * 2;
    const int v1 = v0 + 1;
    const bool p0 = v0 < VOCAB;
    const bool p1 = v1 < VOCAB;

    const uint4* w0 = (const uint4*)(g_wout_h + (size_t)v0 * HID);
    const uint4* w1 = (const uint4*)(g_wout_h + (size_t)v1 * HID);

    float acc0 = 0.f, acc1 = 0.f;
    #pragma unroll
    for (int it = 0; it < 8; it++) {                    // 2048 halves / (32 lanes * 8) = 8
        int idx = it * 32 + lane;
        float4 ha = sh4[2 * idx];
        float4 hb = sh4[2 * idx + 1];
        if (p0) {
            uint4 wv = __ldcs(&w0[idx]);
            float2 f0 = __half22float2(*(__half2*)&wv.x);
            float2 f1 = __half22float2(*(__half2*)&wv.y);
            float2 f2 = __half22float2(*(__half2*)&wv.z);
            float2 f3 = __half22float2(*(__half2*)&wv.w);
            acc0 += f0.x * ha.x + f0.y * ha.y + f1.x * ha.z + f1.y * ha.w
                  + f2.x * hb.x + f2.y * hb.y + f3.x * hb.z + f3.y * hb.w;
        }
        if (p1) {
            uint4 wv = __ldcs(&w1[idx]);
            float2 f0 = __half22float2(*(__half2*)&wv.x);
            float2 f1 = __half22float2(*(__half2*)&wv.y);
            float2 f2 = __half22float2(*(__half2*)&wv.z);
            float2 f3 = __half22float2(*(__half2*)&wv.w);
            acc1 += f0.x * ha.x + f0.y * ha.y + f1.x * ha.z + f1.y * ha.w
                  + f2.x * hb.x + f2.y * hb.y + f3.x * hb.z + f3.y * hb.w;
        }
    }
    #pragma unroll
    for (int off = 16; off > 0; off >>= 1) {
        acc0 += __shfl_xor_sync(0xFFFFFFFFu, acc0, off);
        acc1 += __shfl_xor_sync(0xFFFFFFFFu, acc1, off);
    }
    if (lane == 0 && p0) __stcs(&out[(size_t)t * VOCAB + v0], acc0 + __ldg(&b_out[v0]));
    if (lane == 0 && p1) __stcs(&out[(size_t)t * VOCAB + v1], acc1 + __ldg(&b_out[v1]));
}

// Parallel refine: each of 32 blocks finds its slice's approx-top-3, recomputes
// those exactly in fp32, and atomicMaxes the exact packed key. Global result =
// exact argmax with first-index tie rule. Grid: REFINE_BLOCKS x 256.
__global__ void __launch_bounds__(256) refine_kernel(
    const float* __restrict__ W_out,
    const float* __restrict__ b_out,
    const float* __restrict__ out,
    int t)
{
    __shared__ unsigned long long stop[8][3];
    __shared__ unsigned long long gtop[3];
    __shared__ unsigned long long res[3];

    const int tid  = threadIdx.x;
    const int lane = tid & 31;
    const int warp = tid >> 5;
    const float* lg = out + (size_t)t * VOCAB;

    const int vbeg = blockIdx.x * REFINE_CHUNK;
    const int vend = min(vbeg + REFINE_CHUNK, VOCAB);

    unsigned long long k0 = 0, k1 = 0, k2 = 0;
    for (int v = vbeg + tid; v < vend; v += 256) {
        unsigned long long key = pack_key(__ldcg(&lg[v]), v);
        if (key > k0)      { k2 = k1; k1 = k0; k0 = key; }
        else if (key > k1) { k2 = k1; k1 = key; }
        else if (key > k2) { k2 = key; }
    }
    #pragma unroll
    for (int r = 0; r < 3; r++) {
        unsigned long long m = k0;
        #pragma unroll
        for (int off = 16; off > 0; off >>= 1) {
            unsigned long long o = __shfl_xor_sync(0xFFFFFFFFu, m, off);
            if (o > m) m = o;
        }
        if (k0 == m) { k0 = k1; k1 = k2; k2 = 0; }
        if (lane == 0) stop[warp][r] = m;
    }
    __syncthreads();
    if (warp == 0) {
        k0 = (lane < 8) ? stop[lane][0] : 0;
        k1 = (lane < 8) ? stop[lane][1] : 0;
        k2 = (lane < 8) ? stop[lane][2] : 0;
        #pragma unroll
        for (int r = 0; r < 3; r++) {
            unsigned long long m = k0;
            #pragma unroll
            for (int off = 16; off > 0; off >>= 1) {
                unsigned long long o = __shfl_xor_sync(0xFFFFFFFFu, m, off);
                if (o > m) m = o;
            }
            if (k0 == m) { k0 = k1; k1 = k2; k2 = 0; }
            if (lane == 0) gtop[r] = m;
        }
    }
    __syncthreads();

    if (warp < 3) {
        unsigned long long key = gtop[warp];
        int v = (int)(0xFFFFFFFFu - (unsigned)(key & 0xFFFFFFFFull));
        const float4* w  = (const float4*)(W_out + (size_t)v * HID);
        const float4* h4 = (const float4*)(g_h[(t + 1) & 1]);
        float acc = 0.f;
        #pragma unroll
        for (int it = 0; it < 16; it++) {
            int idx = it * 32 + lane;
            float4 wv = __ldg(&w[idx]);
            float4 hv = __ldg(&h4[idx]);
            acc += wv.x * hv.x + wv.y * hv.y + wv.z * hv.z + wv.w * hv.w;
        }
        #pragma unroll
        for (int off = 16; off > 0; off >>= 1)
            acc += __shfl_xor_sync(0xFFFFFFFFu, acc, off);
        if (lane == 0) res[warp] = pack_key(acc + __ldg(&b_out[v]), v);
    }
    __syncthreads();
    if (tid == 0) {
        unsigned long long best = res[0];
        if (res[1] > best) best = res[1];
        if (res[2] > best) best = res[2];
        atomicMax(&g_key[t & 1], best);
    }
}

extern "C" void kernel_launch(void* const* d_in, const int* in_sizes, int n_in,
                              void* d_out, int out_size)
{
    const float* emb   = (const float*)d_in[0];
    const float* W_ih  = (const float*)d_in[1];
    const float* W_hh  = (const float*)d_in[2];
    const float* b_ih  = (const float*)d_in[3];
    const float* b_hh  = (const float*)d_in[4];
    const float* W_out = (const float*)d_in[5];
    const float* b_out = (const float*)d_in[6];
    float* out = (float*)d_out;

    init_kernel<<<2, 1024>>>();
    wout_convert_kernel<<<VOCAB, 256>>>(W_out);

    for (int t = 0; t < T_STEPS; t++) {
        gates_x_cell_kernel<<<512, 256>>>(emb, W_ih, b_ih, b_hh, t);
        fused_logits_gh_kernel<<<FUSED_BLOCKS, 256>>>(W_hh, b_out, out, t);
        refine_kernel<<<REFINE_BLOCKS, 256>>>(W_out, b_out, out, t);
    }
}

// round 9
// speedup vs baseline: 1.6357x; 1.2089x over previous
#include <cuda_runtime.h>
#include <cuda_fp16.h>
#include <math.h>

#define EMB   1024
#define HID   2048
#define VOCAB 50257
#define T_STEPS 256
#define GH_BLOCKS 512
#define LOGIT_BLOCKS ((VOCAB + 15) / 16)
#define FUSED_BLOCKS (GH_BLOCKS + LOGIT_BLOCKS)
#define REFINE_BLOCKS 32
#define REFINE_CHUNK ((VOCAB + REFINE_BLOCKS - 1) / REFINE_BLOCKS)

// Persistent state. h double-buffered; c in-place; g_key = packed argmax
// (orderable float bits << 32 | (0xFFFFFFFF - index)), double-buffered.
__device__ __align__(16) float g_h[2][HID];
__device__ __align__(16) float g_c[HID];
__device__ unsigned long long g_key[2];
__device__ __align__(16) float g_gh[4 * HID];   // h . W_hh partials (row-indexed)

// fp16 weight copies (scratch via __device__ globals, per harness rules).
__device__ __align__(16) __half g_wout_h[(size_t)VOCAB * HID];   // 206 MB
__device__ __align__(16) __half g_whh_h[(size_t)4 * HID * HID];  // 32 MB
__device__ __align__(16) __half g_wih_h[(size_t)4 * HID * EMB];  // 16 MB

__device__ __forceinline__ float sigmoidf_(float x) {
    return 1.0f / (1.0f + expf(-x));
}

__device__ __forceinline__ unsigned long long pack_key(float v, int idx) {
    unsigned ub = __float_as_uint(v);
    unsigned mk = (ub & 0x80000000u) ? ~ub : (ub | 0x80000000u);  // orderable float
    return ((unsigned long long)mk << 32) | (unsigned long long)(0xFFFFFFFFu - (unsigned)idx);
}

// fp16 uint4 (8 halves) dot 8 shared floats, fp32 accumulate.
__device__ __forceinline__ float dot8_h(uint4 wv, float4 ha, float4 hb) {
    float2 f0 = __half22float2(*(__half2*)&wv.x);
    float2 f1 = __half22float2(*(__half2*)&wv.y);
    float2 f2 = __half22float2(*(__half2*)&wv.z);
    float2 f3 = __half22float2(*(__half2*)&wv.w);
    return f0.x * ha.x + f0.y * ha.y + f1.x * ha.z + f1.y * ha.w
         + f2.x * hb.x + f2.y * hb.y + f3.x * hb.z + f3.y * hb.w;
}

__global__ void init_kernel() {
    int tid = blockIdx.x * blockDim.x + threadIdx.x;
    for (int i = tid; i < HID; i += 2048) {
        g_h[0][i] = 0.0f;
        g_h[1][i] = 0.0f;
        g_c[i]    = 0.0f;
    }
    for (int i = tid; i < 4 * HID; i += 2048) g_gh[i] = 0.0f;  // h0 = 0 -> gh = 0
    if (tid == 0) {
        g_key[0] = 0ull;
        g_key[1] = 0xFFFFFFFFull;  // decodes to token 0 for step 0
    }
}

// Generic fp32 -> fp16 convert: which = 0 (W_out), 1 (W_hh), 2 (W_ih).
// One uint4 (8 halves) per thread; n8 = element count / 8.
__global__ void __launch_bounds__(256) convert_fp16_kernel(
    const float* __restrict__ src, int which, size_t n8)
{
    size_t i = (size_t)blockIdx.x * 256 + threadIdx.x;
    if (i >= n8) return;
    __half* dst = (which == 0) ? g_wout_h : (which == 1) ? g_whh_h : g_wih_h;
    const float4* p = (const float4*)src + 2 * i;
    float4 a = __ldcs(p);
    float4 b = __ldcs(p + 1);
    __half2 h0 = __floats2half2_rn(a.x, a.y);
    __half2 h1 = __floats2half2_rn(a.z, a.w);
    __half2 h2 = __floats2half2_rn(b.x, b.y);
    __half2 h3 = __floats2half2_rn(b.z, b.w);
    uint4 o;
    o.x = *(unsigned*)&h0; o.y = *(unsigned*)&h1;
    o.z = *(unsigned*)&h2; o.w = *(unsigned*)&h3;
    ((uint4*)dst)[i] = o;
}

// gates_x_cell: x . W_ih (fp16) + gh + biases -> nonlinearities -> h, c.
// Also resets the argmax accumulator this step's refine will use.
// Grid: 512 blocks x 256 threads (4 j per block, split-K x2).
__global__ void __launch_bounds__(256) gates_x_cell_kernel(
    const float* __restrict__ emb,
    const float* __restrict__ b_ih,
    const float* __restrict__ b_hh,
    int t)
{
    __shared__ __align__(16) float sx[EMB];
    __shared__ float spart[8][4];

    const int tid  = threadIdx.x;
    const int lane = tid & 31;
    const int warp = tid >> 5;
    const int jl   = warp >> 1;
    const int half = warp & 1;

    unsigned long long key = g_key[(t + 1) & 1];
    int tok = (int)(0xFFFFFFFFu - (unsigned)(key & 0xFFFFFFFFull));
    if (blockIdx.x == 0 && tid == 0) g_key[t & 1] = 0ull;  // refine(t) accumulates here

    const float4* xe = (const float4*)(emb + (size_t)tok * EMB);
    ((float4*)sx)[tid] = xe[tid];
    __syncthreads();

    const int j = blockIdx.x * 4 + jl;
    const int base = half * (EMB / 2);                  // element offset (512)

    float a0 = 0.f, a1 = 0.f, a2 = 0.f, a3 = 0.f;
    const uint4* wi0 = (const uint4*)(g_wih_h + (size_t)(j          ) * EMB + base);
    const uint4* wi1 = (const uint4*)(g_wih_h + (size_t)(j +     HID) * EMB + base);
    const uint4* wi2 = (const uint4*)(g_wih_h + (size_t)(j + 2 * HID) * EMB + base);
    const uint4* wi3 = (const uint4*)(g_wih_h + (size_t)(j + 3 * HID) * EMB + base);
    #pragma unroll
    for (int it = 0; it < 2; it++) {                    // 512 halves / (32*8) = 2
        int idx = it * 32 + lane;
        float4 xa = *(const float4*)(sx + base + idx * 8);
        float4 xb = *(const float4*)(sx + base + idx * 8 + 4);
        a0 += dot8_h(__ldg(&wi0[idx]), xa, xb);
        a1 += dot8_h(__ldg(&wi1[idx]), xa, xb);
        a2 += dot8_h(__ldg(&wi2[idx]), xa, xb);
        a3 += dot8_h(__ldg(&wi3[idx]), xa, xb);
    }

    #pragma unroll
    for (int off = 16; off > 0; off >>= 1) {
        a0 += __shfl_xor_sync(0xFFFFFFFFu, a0, off);
        a1 += __shfl_xor_sync(0xFFFFFFFFu, a1, off);
        a2 += __shfl_xor_sync(0xFFFFFFFFu, a2, off);
        a3 += __shfl_xor_sync(0xFFFFFFFFu, a3, off);
    }
    if (lane == 0) {
        spart[warp][0] = a0; spart[warp][1] = a1;
        spart[warp][2] = a2; spart[warp][3] = a3;
    }
    __syncthreads();

    if (tid < 4) {
        const int jj = blockIdx.x * 4 + tid;
        const int w0 = 2 * tid;
        float s0 = spart[w0][0] + spart[w0 + 1][0] + g_gh[jj          ]
                 + b_ih[jj          ] + b_hh[jj          ];
        float s1 = spart[w0][1] + spart[w0 + 1][1] + g_gh[jj +     HID]
                 + b_ih[jj +     HID] + b_hh[jj +     HID];
        float s2 = spart[w0][2] + spart[w0 + 1][2] + g_gh[jj + 2 * HID]
                 + b_ih[jj + 2 * HID] + b_hh[jj + 2 * HID];
        float s3 = spart[w0][3] + spart[w0 + 1][3] + g_gh[jj + 3 * HID]
                 + b_ih[jj + 3 * HID] + b_hh[jj + 3 * HID];
        float ig = sigmoidf_(s0);
        float fg = sigmoidf_(s1);
        float gg = tanhf(s2);
        float og = sigmoidf_(s3);
        float c  = fg * g_c[jj] + ig * gg;
        g_c[jj] = c;
        g_h[(t + 1) & 1][jj] = og * tanhf(c);
    }
}

// Fused kernel: blocks [0, GH_BLOCKS) compute gh = h(t+1) . W_hh (fp16, feeds
// step t+1); blocks [GH_BLOCKS, FUSED_BLOCKS) compute this step's fp16 logits.
// Both depend only on h(t+1). __launch_bounds__(256, 6) keeps occupancy high.
__global__ void __launch_bounds__(256, 6) fused_logits_gh_kernel(
    const float* __restrict__ b_out,
    float* __restrict__ out,
    int t)
{
    __shared__ __align__(16) float sh[HID];
    __shared__ float spart[8][4];

    const int tid  = threadIdx.x;
    const int lane = tid & 31;
    const int warp = tid >> 5;

    const float4* h4 = (const float4*)(g_h[(t + 1) & 1]);
    ((float4*)sh)[tid]       = h4[tid];
    ((float4*)sh)[tid + 256] = h4[tid + 256];
    __syncthreads();

    const float4* sh4 = (const float4*)sh;

    if (blockIdx.x < GH_BLOCKS) {
        // ---- gh part: 4 j per block, split-K x2, fp16 uint4 loads ----
        const int jl   = warp >> 1;
        const int half = warp & 1;
        const int j    = blockIdx.x * 4 + jl;
        const int base = half * (HID / 2);              // element offset (1024)

        float a0 = 0.f, a1 = 0.f, a2 = 0.f, a3 = 0.f;
        const uint4* wh0 = (const uint4*)(g_whh_h + (size_t)(j          ) * HID + base);
        const uint4* wh1 = (const uint4*)(g_whh_h + (size_t)(j +     HID) * HID + base);
        const uint4* wh2 = (const uint4*)(g_whh_h + (size_t)(j + 2 * HID) * HID + base);
        const uint4* wh3 = (const uint4*)(g_whh_h + (size_t)(j + 3 * HID) * HID + base);
        #pragma unroll
        for (int it = 0; it < 4; it++) {                // 1024 halves / (32*8) = 4
            int idx = it * 32 + lane;
            float4 ha = *(const float4*)(sh + base + idx * 8);
            float4 hb = *(const float4*)(sh + base + idx * 8 + 4);
            a0 += dot8_h(__ldg(&wh0[idx]), ha, hb);
            a1 += dot8_h(__ldg(&wh1[idx]), ha, hb);
            a2 += dot8_h(__ldg(&wh2[idx]), ha, hb);
            a3 += dot8_h(__ldg(&wh3[idx]), ha, hb);
        }

        #pragma unroll
        for (int off = 16; off > 0; off >>= 1) {
            a0 += __shfl_xor_sync(0xFFFFFFFFu, a0, off);
            a1 += __shfl_xor_sync(0xFFFFFFFFu, a1, off);
            a2 += __shfl_xor_sync(0xFFFFFFFFu, a2, off);
            a3 += __shfl_xor_sync(0xFFFFFFFFu, a3, off);
        }
        if (lane == 0) {
            spart[warp][0] = a0; spart[warp][1] = a1;
            spart[warp][2] = a2; spart[warp][3] = a3;
        }
        __syncthreads();

        if (tid < 4) {
            const int jj = blockIdx.x * 4 + tid;
            const int w0 = 2 * tid;
            g_gh[jj          ] = spart[w0][0] + spart[w0 + 1][0];
            g_gh[jj +     HID] = spart[w0][1] + spart[w0 + 1][1];
            g_gh[jj + 2 * HID] = spart[w0][2] + spart[w0 + 1][2];
            g_gh[jj + 3 * HID] = spart[w0][3] + spart[w0 + 1][3];
        }
        return;
    }

    // ---- logits part: 2 rows/warp, uint4 __ldcs streaming loads ----
    const int lb = blockIdx.x - GH_BLOCKS;
    const int v0 = lb * 16 + warp * 2;
    const int v1 = v0 + 1;
    const bool p0 = v0 < VOCAB;
    const bool p1 = v1 < VOCAB;

    const uint4* w0 = (const uint4*)(g_wout_h + (size_t)v0 * HID);
    const uint4* w1 = (const uint4*)(g_wout_h + (size_t)v1 * HID);

    float acc0 = 0.f, acc1 = 0.f;
    #pragma unroll
    for (int it = 0; it < 8; it++) {                    // 2048 halves / (32 lanes * 8) = 8
        int idx = it * 32 + lane;
        float4 ha = sh4[2 * idx];
        float4 hb = sh4[2 * idx + 1];
        if (p0) acc0 += dot8_h(__ldcs(&w0[idx]), ha, hb);
        if (p1) acc1 += dot8_h(__ldcs(&w1[idx]), ha, hb);
    }
    #pragma unroll
    for (int off = 16; off > 0; off >>= 1) {
        acc0 += __shfl_xor_sync(0xFFFFFFFFu, acc0, off);
        acc1 += __shfl_xor_sync(0xFFFFFFFFu, acc1, off);
    }
    if (lane == 0 && p0) __stcs(&out[(size_t)t * VOCAB + v0], acc0 + __ldg(&b_out[v0]));
    if (lane == 0 && p1) __stcs(&out[(size_t)t * VOCAB + v1], acc1 + __ldg(&b_out[v1]));
}

// Parallel refine: each of 32 blocks finds its slice's approx-top-3, recomputes
// those exactly in fp32, and atomicMaxes the exact packed key. Global result =
// exact argmax with first-index tie rule. Grid: REFINE_BLOCKS x 256.
__global__ void __launch_bounds__(256) refine_kernel(
    const float* __restrict__ W_out,
    const float* __restrict__ b_out,
    const float* __restrict__ out,
    int t)
{
    __shared__ unsigned long long stop[8][3];
    __shared__ unsigned long long gtop[3];
    __shared__ unsigned long long res[3];

    const int tid  = threadIdx.x;
    const int lane = tid & 31;
    const int warp = tid >> 5;
    const float* lg = out + (size_t)t * VOCAB;

    const int vbeg = blockIdx.x * REFINE_CHUNK;
    const int vend = min(vbeg + REFINE_CHUNK, VOCAB);

    unsigned long long k0 = 0, k1 = 0, k2 = 0;
    for (int v = vbeg + tid; v < vend; v += 256) {
        unsigned long long key = pack_key(__ldcg(&lg[v]), v);
        if (key > k0)      { k2 = k1; k1 = k0; k0 = key; }
        else if (key > k1) { k2 = k1; k1 = key; }
        else if (key > k2) { k2 = key; }
    }
    #pragma unroll
    for (int r = 0; r < 3; r++) {
        unsigned long long m = k0;
        #pragma unroll
        for (int off = 16; off > 0; off >>= 1) {
            unsigned long long o = __shfl_xor_sync(0xFFFFFFFFu, m, off);
            if (o > m) m = o;
        }
        if (k0 == m) { k0 = k1; k1 = k2; k2 = 0; }
        if (lane == 0) stop[warp][r] = m;
    }
    __syncthreads();
    if (warp == 0) {
        k0 = (lane < 8) ? stop[lane][0] : 0;
        k1 = (lane < 8) ? stop[lane][1] : 0;
        k2 = (lane < 8) ? stop[lane][2] : 0;
        #pragma unroll
        for (int r = 0; r < 3; r++) {
            unsigned long long m = k0;
            #pragma unroll
            for (int off = 16; off > 0; off >>= 1) {
                unsigned long long o = __shfl_xor_sync(0xFFFFFFFFu, m, off);
                if (o > m) m = o;
            }
            if (k0 == m) { k0 = k1; k1 = k2; k2 = 0; }
            if (lane == 0) gtop[r] = m;
        }
    }
    __syncthreads();

    if (warp < 3) {
        unsigned long long key = gtop[warp];
        int v = (int)(0xFFFFFFFFu - (unsigned)(key & 0xFFFFFFFFull));
        const float4* w  = (const float4*)(W_out + (size_t)v * HID);
        const float4* h4 = (const float4*)(g_h[(t + 1) & 1]);
        float acc = 0.f;
        #pragma unroll
        for (int it = 0; it < 16; it++) {
            int idx = it * 32 + lane;
            float4 wv = __ldg(&w[idx]);
            float4 hv = __ldg(&h4[idx]);
            acc += wv.x * hv.x + wv.y * hv.y + wv.z * hv.z + wv.w * hv.w;
        }
        #pragma unroll
        for (int off = 16; off > 0; off >>= 1)
            acc += __shfl_xor_sync(0xFFFFFFFFu, acc, off);
        if (lane == 0) res[warp] = pack_key(acc + __ldg(&b_out[v]), v);
    }
    __syncthreads();
    if (tid == 0) {
        unsigned long long best = res[0];
        if (res[1] > best) best = res[1];
        if (res[2] > best) best = res[2];
        atomicMax(&g_key[t & 1], best);
    }
}

extern "C" void kernel_launch(void* const* d_in, const int* in_sizes, int n_in,
                              void* d_out, int out_size)
{
    const float* emb   = (const float*)d_in[0];
    const float* W_ih  = (const float*)d_in[1];
    const float* W_hh  = (const float*)d_in[2];
    const float* b_ih  = (const float*)d_in[3];
    const float* b_hh  = (const float*)d_in[4];
    const float* W_out = (const float*)d_in[5];
    const float* b_out = (const float*)d_in[6];
    float* out = (float*)d_out;

    init_kernel<<<2, 1024>>>();
    {
        size_t n8;
        n8 = (size_t)VOCAB * HID / 8;
        convert_fp16_kernel<<<(unsigned)((n8 + 255) / 256), 256>>>(W_out, 0, n8);
        n8 = (size_t)4 * HID * HID / 8;
        convert_fp16_kernel<<<(unsigned)((n8 + 255) / 256), 256>>>(W_hh, 1, n8);
        n8 = (size_t)4 * HID * EMB / 8;
        convert_fp16_kernel<<<(unsigned)((n8 + 255) / 256), 256>>>(W_ih, 2, n8);
    }

    for (int t = 0; t < T_STEPS; t++) {
        gates_x_cell_kernel<<<512, 256>>>(emb, b_ih, b_hh, t);
        fused_logits_gh_kernel<<<FUSED_BLOCKS, 256>>>(b_out, out, t);
        refine_kernel<<<REFINE_BLOCKS, 256>>>(W_out, b_out, out, t);
    }
}